// round 5
// baseline (speedup 1.0000x reference)
#include <cuda_runtime.h>
#include <cuda_bf16.h>
#include <cstdint>

// Problem: N=2048, D=128, k=4, T=0.5.
// queries rows = 4096, keys cols = 8192.
// sim = norm(z[0:4096]) @ norm(z_all)^T * 2 ; mask non-target diagonals;
// loss = mean(logsumexp - pos). Logits bounded in [-2,2] -> no max needed.
// Strategy: sum exp over ALL columns, then subtract the (single per row per
// CTA) masked diagonal exp afterwards — removes per-element predicates.

#define DIMK 128

// ---------------- device scratch (no allocations allowed) -------------------
__device__ __nv_bfloat16 g_nb[8192 * 128];  // normalized rows, bf16
__device__ float g_S[8 * 4096];             // per (colgroup,row) exp-sum
__device__ float g_pos[8 * 4096];           // per (colgroup,row) positive logit

__device__ __forceinline__ uint32_t smem_u32(const void* p) {
    uint32_t a;
    asm("{ .reg .u64 t; cvta.to.shared.u64 t, %1; cvt.u32.u64 %0, t; }"
        : "=r"(a) : "l"(p));
    return a;
}
__device__ __forceinline__ float ex2(float x) {
    float y;
    asm("ex2.approx.ftz.f32 %0, %1;" : "=f"(y) : "f"(x));
    return y;
}
__device__ __forceinline__ void ldsm_x4(uint32_t* r, uint32_t addr) {
    asm volatile("ldmatrix.sync.aligned.m8n8.x4.shared.b16 {%0,%1,%2,%3}, [%4];"
                 : "=r"(r[0]), "=r"(r[1]), "=r"(r[2]), "=r"(r[3]) : "r"(addr));
}
__device__ __forceinline__ void mma16816(float* c, const uint32_t* a,
                                         uint32_t b0, uint32_t b1) {
    asm volatile(
        "mma.sync.aligned.m16n8k16.row.col.f32.bf16.bf16.f32 "
        "{%0,%1,%2,%3}, {%4,%5,%6,%7}, {%8,%9}, {%0,%1,%2,%3};"
        : "+f"(c[0]), "+f"(c[1]), "+f"(c[2]), "+f"(c[3])
        : "r"(a[0]), "r"(a[1]), "r"(a[2]), "r"(a[3]), "r"(b0), "r"(b1));
}

#define CP_ASYNC16(sm, gp) \
    asm volatile("cp.async.cg.shared.global [%0], [%1], 16;" :: "r"(sm), "l"(gp))
#define CP_COMMIT() asm volatile("cp.async.commit_group;" ::: "memory")
#define CP_WAIT_ALL() asm volatile("cp.async.wait_all;" ::: "memory")

#define C2LOG2E 2.885390081777927f   // 2 * log2(e)  (1/T = 2 folded into exp2)

// ---------------------------------------------------------------------------
// Kernel 1: L2-normalize 8192 rows -> bf16. 4 rows per warp (MLP=4).
// grid 256 x 256.
// ---------------------------------------------------------------------------
__global__ void normalize_kernel(const float* __restrict__ a1,
                                 const float* __restrict__ a2,
                                 const float* __restrict__ a3,
                                 const float* __restrict__ a4) {
    int w = threadIdx.x >> 5, lane = threadIdx.x & 31;
    int row0 = blockIdx.x * 32 + w * 4;
    float4 v[4];
    float ss[4];
#pragma unroll
    for (int i = 0; i < 4; i++) {
        int row = row0 + i;
        const float* src = (row < 2048) ? a1 : (row < 4096) ? a2
                          : (row < 6144) ? a3 : a4;
        v[i] = *(const float4*)(src + (row & 2047) * DIMK + lane * 4);
        ss[i] = v[i].x * v[i].x + v[i].y * v[i].y + v[i].z * v[i].z + v[i].w * v[i].w;
    }
#pragma unroll
    for (int off = 16; off; off >>= 1) {
#pragma unroll
        for (int i = 0; i < 4; i++) ss[i] += __shfl_xor_sync(~0u, ss[i], off);
    }
#pragma unroll
    for (int i = 0; i < 4; i++) {
        float inv = 1.0f / fmaxf(sqrtf(ss[i]), 1e-8f);
        __nv_bfloat162 p0 = __float22bfloat162_rn(make_float2(v[i].x * inv, v[i].y * inv));
        __nv_bfloat162 p1 = __float22bfloat162_rn(make_float2(v[i].z * inv, v[i].w * inv));
        uint2 st;
        st.x = *(uint32_t*)&p0;
        st.y = *(uint32_t*)&p1;
        ((uint2*)(g_nb + (row0 + i) * DIMK))[lane] = st;
    }
}

// ---------------------------------------------------------------------------
// Kernel 2: HMMA bf16 GEMM. CTA tile = 128 rows x 1024 cols (8 subtiles of
// 128), K=128 in one shot. A loaded once; B double-buffered via cp.async.
// 256 threads = 8 warps (4 M x 2 N), warp tile 32x64.
// grid = (32 row tiles, 8 col groups) = 256 CTAs -> ONE wave at 2 CTA/SM.
// Row exp-sums accumulate in registers across all 8 subtiles.
// ---------------------------------------------------------------------------
#define TSTRIDE 272                 // bytes per SMEM tile row (128 bf16 + 8 pad)
#define SM_A 0
#define SM_B0 (128 * TSTRIDE)       // 34816
#define SM_B1 (2 * 128 * TSTRIDE)   // 69632
#define SM_S (3 * 128 * TSTRIDE)    // 104448: float sS[2][128]
#define SM_P (SM_S + 1024)
#define SMEM_BYTES (SM_P + 1024)    // 106496 (x2 CTA = 208K <= 228K)

__device__ __forceinline__ void issue_tile_load(uint32_t sb, int sm_off,
                                                int grow0, int tid) {
#pragma unroll
    for (int it = 0; it < 8; it++) {
        int idx = it * 256 + tid;           // 2048 16B vectors
        int r = idx >> 4, g = idx & 15;
        CP_ASYNC16(sb + sm_off + r * TSTRIDE + g * 16,
                   (const char*)(g_nb + (grow0 + r) * DIMK + g * 8));
    }
}

__global__ void __launch_bounds__(256, 2) sim_kernel() {
    extern __shared__ char smem[];
    uint32_t sb = smem_u32(smem);
    float* sS = (float*)(smem + SM_S);
    float* sP = (float*)(smem + SM_P);

    int tid = threadIdx.x;
    int lane = tid & 31;
    int w = tid >> 5;
    int wm = w & 3;        // M warp (rows wm*32..+31)
    int wn = w >> 2;       // N warp (cols wn*64..+63)
    int row0 = blockIdx.x * 128;
    int cg = blockIdx.y;                  // cols [cg*1024, cg*1024+1024)

    // ---- prologue: A + B0 ----
    issue_tile_load(sb, SM_A, row0, tid);
    issue_tile_load(sb, SM_B0, cg * 1024, tid);
    CP_COMMIT();

    // ---- ldmatrix lane address bases ----
    int arow = wm * 32 + ((lane >> 3) & 1) * 8 + (lane & 7);
    int akoct = (lane >> 4) * 8;
    uint32_t baseA = sb + SM_A + arow * TSTRIDE + akoct * 2;
    int brow = wn * 64 + ((lane >> 4) & 1) * 8 + (lane & 7);
    int bkoct = ((lane >> 3) & 1) * 8;
    uint32_t baseBoff = brow * TSTRIDE + bkoct * 2;

    int qrow = lane >> 2;          // 0..7
    // ---- per-row diagonal bookkeeping (CTA-uniform parts) ----
    int half = row0 >> 11;                       // row block within one half
    int cblk = cg >> 1;                          // CTA cols within one 2048-blk
    bool tgt = (cblk == 1 - half);
    int dl0 = (row0 & 2047) - (cg & 1) * 1024;   // diag col (CTA-local) of row_local 0

    // per-(mi,h) row data
    int dl[4], nid[4], c_id[4], dsub[4];
    bool fix[4];
#pragma unroll
    for (int mi = 0; mi < 2; mi++)
#pragma unroll
        for (int h = 0; h < 2; h++) {
            int i = mi * 2 + h;
            int row_local = wm * 32 + mi * 16 + qrow + 8 * h;
            int d = dl0 + row_local;             // diag col within CTA cols
            dl[i] = d;
            dsub[i] = d >> 7;                    // which subtile holds it
            nid[i] = (d & 63) >> 3;
            c_id[i] = 2 * h + (d & 1);
            fix[i] = (d >= 0) && (d < 1024)
                   && (((d >> 6) & 1) == wn)
                   && (((d & 7) >> 1) == (lane & 3));
        }

    float sumReg[4] = {0.f, 0.f, 0.f, 0.f};
    float posReg[4] = {0.f, 0.f, 0.f, 0.f};

    for (int ct = 0; ct < 8; ct++) {
        CP_WAIT_ALL();
        __syncthreads();           // B(ct) visible; all warps done with ct-1

        if (ct < 7) {              // prefetch B(ct+1), overlapped with compute
            issue_tile_load(sb, ((ct + 1) & 1) ? SM_B1 : SM_B0,
                            cg * 1024 + (ct + 1) * 128, tid);
            CP_COMMIT();
        }

        uint32_t baseB = sb + ((ct & 1) ? SM_B1 : SM_B0) + baseBoff;

        float acc[2][8][4];
#pragma unroll
        for (int mi = 0; mi < 2; mi++)
#pragma unroll
            for (int ni = 0; ni < 8; ni++)
#pragma unroll
                for (int c = 0; c < 4; c++) acc[mi][ni][c] = 0.f;

#pragma unroll
        for (int ks = 0; ks < 8; ks++) {
            uint32_t a[2][4];
            ldsm_x4(a[0], baseA + ks * 32);
            ldsm_x4(a[1], baseA + 16 * TSTRIDE + ks * 32);
            uint32_t b[4][4];
#pragma unroll
            for (int nip = 0; nip < 4; nip++)
                ldsm_x4(b[nip], baseB + nip * 16 * TSTRIDE + ks * 32);
#pragma unroll
            for (int mi = 0; mi < 2; mi++)
#pragma unroll
                for (int nip = 0; nip < 4; nip++) {
                    mma16816(acc[mi][2 * nip + 0], a[mi], b[nip][0], b[nip][1]);
                    mma16816(acc[mi][2 * nip + 1], a[mi], b[nip][2], b[nip][3]);
                }
        }

        // ---- epilogue: branch-free exp-sum, then one diag fixup per row ----
#pragma unroll
        for (int mi = 0; mi < 2; mi++)
#pragma unroll
            for (int h = 0; h < 2; h++) {
                int i = mi * 2 + h;
                float s = 0.f;
#pragma unroll
                for (int ni = 0; ni < 8; ni++) {
                    s += ex2(acc[mi][ni][2 * h + 0] * C2LOG2E);
                    s += ex2(acc[mi][ni][2 * h + 1] * C2LOG2E);
                }
                sumReg[i] += s;
                if (fix[i] && dsub[i] == ct) {
                    float vd = acc[mi][nid[i]][c_id[i]];
                    if (tgt) posReg[i] += vd * 2.0f;           // positive logit
                    else sumReg[i] -= ex2(vd * C2LOG2E);       // masked diag
                }
            }
    }

    // ---- per-row reduce across lanes (cols) and the 2 N warps ----
#pragma unroll
    for (int i = 0; i < 4; i++) {
        sumReg[i] += __shfl_xor_sync(~0u, sumReg[i], 1);
        sumReg[i] += __shfl_xor_sync(~0u, sumReg[i], 2);
        posReg[i] += __shfl_xor_sync(~0u, posReg[i], 1);
        posReg[i] += __shfl_xor_sync(~0u, posReg[i], 2);
    }
    __syncthreads();               // also guards sS/sP region reuse
    if ((lane & 3) == 0) {
#pragma unroll
        for (int mi = 0; mi < 2; mi++)
#pragma unroll
            for (int h = 0; h < 2; h++) {
                int i = mi * 2 + h;
                int row_local = wm * 32 + mi * 16 + qrow + 8 * h;
                sS[wn * 128 + row_local] = sumReg[i];
                sP[wn * 128 + row_local] = posReg[i];
            }
    }
    __syncthreads();
    if (tid < 128) {
        int row = row0 + tid;
        g_S[cg * 4096 + row] = sS[tid] + sS[128 + tid];
        g_pos[cg * 4096 + row] = sP[tid] + sP[128 + tid];
    }
}

// ---------------------------------------------------------------------------
// Kernel 3: fused loss = mean over 4096 rows of log(sum of 8 partials) - pos.
// One block, 1024 threads, 4 rows each.
// ---------------------------------------------------------------------------
__global__ void finalize_kernel(float* __restrict__ out) {
    __shared__ float wsum[32];
    int tid = threadIdx.x;
    int lane = tid & 31, wid = tid >> 5;
    float local = 0.f;
#pragma unroll
    for (int i = 0; i < 4; i++) {
        int row = tid + i * 1024;
        float S = 0.f, p = 0.f;
#pragma unroll
        for (int c = 0; c < 8; c++) {
            S += g_S[c * 4096 + row];
            p += g_pos[c * 4096 + row];
        }
        local += logf(S) - p;
    }
#pragma unroll
    for (int off = 16; off; off >>= 1) local += __shfl_xor_sync(~0u, local, off);
    if (lane == 0) wsum[wid] = local;
    __syncthreads();
    if (wid == 0) {
        float t = wsum[lane];
#pragma unroll
        for (int off = 16; off; off >>= 1) t += __shfl_xor_sync(~0u, t, off);
        if (lane == 0) out[0] = t / 4096.f;
    }
}

// ---------------------------------------------------------------------------
extern "C" void kernel_launch(void* const* d_in, const int* in_sizes, int n_in,
                              void* d_out, int out_size) {
    const float* a1 = (const float*)d_in[0];
    const float* a2 = (const float*)d_in[1];
    const float* a3 = (const float*)d_in[2];
    const float* a4 = (const float*)d_in[3];

    normalize_kernel<<<256, 256>>>(a1, a2, a3, a4);

    cudaFuncSetAttribute(sim_kernel, cudaFuncAttributeMaxDynamicSharedMemorySize,
                         SMEM_BYTES);
    dim3 grid(32, 8);
    sim_kernel<<<grid, 256, SMEM_BYTES>>>();

    finalize_kernel<<<1, 1024>>>((float*)d_out);
}